// round 15
// baseline (speedup 1.0000x reference)
#include <cuda_runtime.h>
#include <cstdint>
#include <cfloat>

#define NPTS 4096
#define BQ_K 32
#define M_PER_B (NPTS * BQ_K)   // max 131072 columns per batch
#define NBATCH 2
#define NCELL 1000               // 10x10x10 grid, cell = 0.1 = radius
#define NBLK 1024                // gemm grid.x (128-col tiles)

// ---------------- scratch (device globals; no allocations) ----------------
__device__ float  g_x0[NBATCH * 13  * M_PER_B];
__device__ float  g_x1[NBATCH * 64  * M_PER_B];
__device__ float  g_x2[NBATCH * 64  * M_PER_B];
__device__ float  g_y2[NBATCH * 128 * M_PER_B];
__device__ float  g_wt[NBATCH * M_PER_B];
__device__ int    g_idx[NBATCH * NPTS * BQ_K];
__device__ int    g_cnt[NBATCH * NPTS];
__device__ int    g_off[NBATCH * NPTS];
__device__ int    g_meta[NBATCH * 2];
__device__ float  g_part[3][NBATCH * NBLK * 8 * 2];
__device__ float  g_mr[3][NBATCH * 8 * 2];
__device__ int    g_cellOff[NBATCH][NCELL + 1];
__device__ float4 g_cellXYZ4[NBATCH * NPTS];     // cell-ordered {x,y,z,idx}

// ---------------- helpers ----------------
__device__ __forceinline__ float lo32(unsigned long long v) {
    return __uint_as_float((unsigned)(v & 0xffffffffull));
}
__device__ __forceinline__ float hi32(unsigned long long v) {
    return __uint_as_float((unsigned)(v >> 32));
}
__device__ __forceinline__ void ffma2(unsigned long long& a,
                                      unsigned long long w,
                                      unsigned long long y) {
    asm("fma.rn.f32x2 %0, %1, %2, %0;" : "+l"(a) : "l"(w), "l"(y));
}
__device__ __forceinline__ uint32_t smem_u32(const void* p) {
    uint32_t a;
    asm("{ .reg .u64 t; cvta.to.shared.u64 t, %1; cvt.u32.u64 %0, t; }"
        : "=r"(a) : "l"(p));
    return a;
}
__device__ __forceinline__ void cp_async16(uint32_t saddr, const void* gptr) {
    asm volatile("cp.async.cg.shared.global [%0], [%1], 16;"
                 :: "r"(saddr), "l"(gptr));
}
#define CP_COMMIT() asm volatile("cp.async.commit_group;")
#define CP_WAIT0()  asm volatile("cp.async.wait_group 0;")

__device__ __forceinline__ float angle3(float ax, float ay, float az,
                                        float bx, float by, float bz) {
    float cx = ay * bz - az * by;
    float cy = az * bx - ax * bz;
    float cz = ax * by - ay * bx;
    float s = cx * cx + cy * cy + cz * cz;
    float y = s > 0.f ? sqrtf(s) : 0.f;
    float x = ax * bx + ay * by + az * bz;
    if (y == 0.f && x == 0.f) return 0.f;
    return atan2f(y, x);
}
__device__ __forceinline__ int cell_of(float x, float y, float z) {
    int cx = (int)(x * 10.f); cx = cx < 0 ? 0 : (cx > 9 ? 9 : cx);
    int cy = (int)(y * 10.f); cy = cy < 0 ? 0 : (cy > 9 ? 9 : cy);
    int cz = (int)(z * 10.f); cz = cz < 0 ? 0 : (cz > 9 ? 9 : cz);
    return (cz * 10 + cy) * 10 + cx;
}

// ---------------- K0: grid build (one block per batch) ----------------
__global__ void __launch_bounds__(1024) grid_build_kernel(
    const float* __restrict__ xyz)
{
    __shared__ int scnt[NCELL];
    __shared__ int sp[1024];
    __shared__ int sbase[NCELL];

    const int b = blockIdx.x;
    const int t = threadIdx.x;
    const float* xb = xyz + (size_t)b * NPTS * 3;

    if (t < NCELL) scnt[t] = 0;
    __syncthreads();

    float px[4], py[4], pz[4];
    int cells[4];
#pragma unroll
    for (int q = 0; q < 4; q++) {
        int i = t * 4 + q;
        px[q] = xb[i * 3 + 0];
        py[q] = xb[i * 3 + 1];
        pz[q] = xb[i * 3 + 2];
        cells[q] = cell_of(px[q], py[q], pz[q]);
        atomicAdd(&scnt[cells[q]], 1);
    }
    __syncthreads();

    sp[t] = (t < NCELL) ? scnt[t] : 0;
    __syncthreads();
    for (int d = 1; d < 1024; d <<= 1) {
        int u = (t >= d) ? sp[t - d] : 0;
        __syncthreads();
        sp[t] += u;
        __syncthreads();
    }
    if (t < NCELL) {
        int e = (t > 0) ? sp[t - 1] : 0;
        sbase[t] = e;
        scnt[t] = 0;
        g_cellOff[b][t] = e;
    }
    if (t == 0) g_cellOff[b][NCELL] = NPTS;
    __syncthreads();

#pragma unroll
    for (int q = 0; q < 4; q++) {
        int i = t * 4 + q;
        int c = cells[q];
        int pos = sbase[c] + atomicAdd(&scnt[c], 1);
        g_cellXYZ4[b * NPTS + pos] =
            make_float4(px[q], py[q], pz[q], __int_as_float(i));
    }
}

// ---------------- K1: ball query via grid (warp per point) ----------------
__global__ void __launch_bounds__(256) ballgrid_kernel(
    const float* __restrict__ xyz)
{
    __shared__ int hitbuf[8][96];

    const int b    = blockIdx.y;
    const int warp = threadIdx.x >> 5;
    const int lane = threadIdx.x & 31;
    const int i    = blockIdx.x * 8 + warp;

    const float cx = __ldg(xyz + ((size_t)b * NPTS + i) * 3 + 0);
    const float cy = __ldg(xyz + ((size_t)b * NPTS + i) * 3 + 1);
    const float cz = __ldg(xyz + ((size_t)b * NPTS + i) * 3 + 2);
    const float R2 = (float)(0.1 * 0.1);

    int cxi = (int)(cx * 10.f); cxi = cxi < 0 ? 0 : (cxi > 9 ? 9 : cxi);
    int cyi = (int)(cy * 10.f); cyi = cyi < 0 ? 0 : (cyi > 9 ? 9 : cyi);
    int czi = (int)(cz * 10.f); czi = czi < 0 ? 0 : (czi > 9 ? 9 : czi);
    const int x0 = cxi > 0 ? cxi - 1 : 0;
    const int x1 = cxi < 9 ? cxi + 1 : 9;

    int* hb = hitbuf[warp];
    int nh = 0;
    const float4* cxyz = g_cellXYZ4 + (size_t)b * NPTS;

    for (int dz = -1; dz <= 1; dz++) {
        int z = czi + dz;
        if (z < 0 || z > 9) continue;
        for (int dy = -1; dy <= 1; dy++) {
            int y = cyi + dy;
            if (y < 0 || y > 9) continue;
            int row = (z * 10 + y) * 10;
            int s = g_cellOff[b][row + x0];
            int e = g_cellOff[b][row + x1 + 1];
            for (int base = s; base < e; base += 32) {
                int idx = base + lane;
                bool v = idx < e;
                float4 q = v ? __ldg(cxyz + idx) : make_float4(9.f, 9.f, 9.f, 0.f);
                float dx = q.x - cx;
                float dyv = q.y - cy;
                float dzv = q.z - cz;
                float d2 = __fadd_rn(__fadd_rn(__fmul_rn(dx, dx),
                                               __fmul_rn(dyv, dyv)),
                                     __fmul_rn(dzv, dzv));
                bool hit = v && (d2 <= R2);
                unsigned m = __ballot_sync(0xffffffffu, hit);
                if (hit) {
                    int pos = nh + __popc(m & ((1u << lane) - 1u));
                    if (pos < 96) hb[pos] = __float_as_int(q.w);
                }
                nh += __popc(m);
            }
        }
    }
    __syncwarp();

    int c;
    if (nh <= 32) {
        int v = (lane < nh) ? hb[lane] : 0x7fffffff;
#pragma unroll
        for (int k = 2; k <= 32; k <<= 1) {
#pragma unroll
            for (int j = k >> 1; j > 0; j >>= 1) {
                int v2 = __shfl_xor_sync(0xffffffffu, v, j);
                bool lower = (lane & j) == 0;
                bool asc   = (lane & k) == 0;
                v = ((asc == lower) == (v < v2)) ? v
                    : (((asc == lower)) ? min(v, v2) : max(v, v2));
            }
        }
        c = nh;
        if (lane < c) g_idx[((size_t)b * NPTS + i) * BQ_K + lane] = v;
    } else {
        if (lane == 0) {
            int n = nh < 96 ? nh : 96;
            for (int a = 1; a < n; a++) {
                int key = hb[a];
                int p = a - 1;
                while (p >= 0 && hb[p] > key) { hb[p + 1] = hb[p]; p--; }
                hb[p + 1] = key;
            }
        }
        __syncwarp();
        c = BQ_K;
        g_idx[((size_t)b * NPTS + i) * BQ_K + lane] = hb[lane];
    }
    if (lane == 0) g_cnt[b * NPTS + i] = c;
}

// ---------------- K2: deterministic block scan of counts (+ tail zeroing) ----
__global__ void __launch_bounds__(1024) scan_kernel()
{
    __shared__ int sp[1024];
    const int t = threadIdx.x;
    const int b = blockIdx.x;
    int4 cv = ((const int4*)(g_cnt + b * NPTS))[t];
    int s0 = cv.x;
    int s1 = s0 + cv.y;
    int s2 = s1 + cv.z;
    int s3 = s2 + cv.w;
    sp[t] = s3;
    __syncthreads();
    for (int d = 1; d < 1024; d <<= 1) {
        int u = (t >= d) ? sp[t - d] : 0;
        __syncthreads();
        sp[t] += u;
        __syncthreads();
    }
    int e = (t > 0) ? sp[t - 1] : 0;
    int base = b * NPTS + t * 4;
    g_off[base + 0] = e;
    g_off[base + 1] = e + s0;
    g_off[base + 2] = e + s1;
    g_off[base + 3] = e + s2;
    int tot = sp[1023];
    int pad = (tot + 255) & ~255;
    if (t == 0) {
        g_meta[b * 2 + 0] = tot;
        g_meta[b * 2 + 1] = pad;
    }
    for (int col = tot + t; col < pad; col += 1024) {
        float* o = g_x0 + (size_t)b * 13 * M_PER_B + col;
#pragma unroll
        for (int r = 0; r < 13; r++) o[r * M_PER_B] = 0.f;
        g_wt[(size_t)b * M_PER_B + col] = 0.f;
    }
}

// ---------------- K3: compacted 13-ch features + weights ----------------
__global__ void __launch_bounds__(256) feat_kernel(
    const float* __restrict__ xyz, const float* __restrict__ feat,
    const float* __restrict__ wa, const float* __restrict__ wb,
    const float* __restrict__ wc)
{
    const int b = blockIdx.y;
    const int warp = threadIdx.x >> 5;
    const int lane = threadIdx.x & 31;
    const int i = blockIdx.x * 8 + warp;

    const int c   = g_cnt[b * NPTS + i];
    const int off = g_off[b * NPTS + i];
    if (lane >= c) return;

    const float* xb = xyz + (size_t)b * NPTS * 3;
    const float* fb = feat + (size_t)b * NPTS * 3;
    int j = g_idx[((size_t)b * NPTS + i) * BQ_K + lane];

    float cx = __ldg(xb + i * 3 + 0), cy = __ldg(xb + i * 3 + 1), cz = __ldg(xb + i * 3 + 2);
    float gx = __ldg(xb + j * 3 + 0), gy = __ldg(xb + j * 3 + 1), gz = __ldg(xb + j * 3 + 2);
    float nx = __ldg(fb + j * 3 + 0), ny = __ldg(fb + j * 3 + 1), nz = __ldg(fb + j * 3 + 2);
    float rx = __ldg(fb + i * 3 + 0), ry = __ldg(fb + i * 3 + 1), rz = __ldg(fb + i * 3 + 2);
    float dx = gx - cx, dy = gy - cy, dz = gz - cz;
    float sq = dx * dx + dy * dy + dz * dz;
    float dist = sq > 0.f ? sqrtf(sq) : 0.f;
    float a1 = angle3(rx, ry, rz, dx, dy, dz);
    float a2 = angle3(nx, ny, nz, dx, dy, dz);
    float a3 = angle3(rx, ry, rz, nx, ny, nz);
    float A = __ldg(wa), Bv = __ldg(wb), Cv = __ldg(wc);

    int col = off + lane;
    float* o = g_x0 + (size_t)b * 13 * M_PER_B + col;
    o[0 * M_PER_B]  = A * cx;  o[1 * M_PER_B]  = A * cy;  o[2 * M_PER_B]  = A * cz;
    o[3 * M_PER_B]  = A * gx;  o[4 * M_PER_B]  = A * gy;  o[5 * M_PER_B]  = A * gz;
    o[6 * M_PER_B]  = Bv * dx; o[7 * M_PER_B]  = Bv * dy; o[8 * M_PER_B]  = Bv * dz;
    o[9 * M_PER_B]  = Bv * dist;
    o[10 * M_PER_B] = Cv * a1; o[11 * M_PER_B] = Cv * a2; o[12 * M_PER_B] = Cv * a3;
    g_wt[(size_t)b * M_PER_B + col] = (lane == 0) ? (float)(33 - c) : 1.f;
}

// 16 FFMA2 block: 8 outputs x 4 cols
#define FMA_CH4(W0, W1, W2, W3, Y0)               \
    do {                                          \
        ffma2(acc[0][0], (W0).x, (Y0).x);         \
        ffma2(acc[0][1], (W0).x, (Y0).y);         \
        ffma2(acc[1][0], (W0).y, (Y0).x);         \
        ffma2(acc[1][1], (W0).y, (Y0).y);         \
        ffma2(acc[2][0], (W1).x, (Y0).x);         \
        ffma2(acc[2][1], (W1).x, (Y0).y);         \
        ffma2(acc[3][0], (W1).y, (Y0).x);         \
        ffma2(acc[3][1], (W1).y, (Y0).y);         \
        ffma2(acc[4][0], (W2).x, (Y0).x);         \
        ffma2(acc[4][1], (W2).x, (Y0).y);         \
        ffma2(acc[5][0], (W2).y, (Y0).x);         \
        ffma2(acc[5][1], (W2).y, (Y0).y);         \
        ffma2(acc[6][0], (W3).x, (Y0).x);         \
        ffma2(acc[6][1], (W3).x, (Y0).y);         \
        ffma2(acc[7][0], (W3).y, (Y0).x);         \
        ffma2(acc[7][1], (W3).y, (Y0).y);         \
    } while (0)

// ---------------- fused GEMM + input GN/ReLU + weighted stats ---------------
// 128-column tiles, O = 64 per launch, 256 threads, 3 CTAs/SM target.
// LAYER 2 runs twice (oofs/gbase select the output half and GN2 group slots).
template <int LAYER>
__global__ void __launch_bounds__(256, 3)
gemm_gn_kernel(const float* __restrict__ W, const float* __restrict__ gamma,
               const float* __restrict__ beta, int gbase, int oofs)
{
    constexpr int C     = (LAYER == 0) ? 13 : 64;
    constexpr int O     = 64;
    constexpr int NT    = 256;
    constexpr bool GN_IN = (LAYER > 0);
    constexpr int NG    = (LAYER == 2) ? 4 : 8;   // groups written per launch

    const int tid = threadIdx.x;
    const int b   = blockIdx.y;
    const int m0  = blockIdx.x * 128;

    if (m0 >= g_meta[b * 2 + 1]) {
        if (tid < NG) {
            float* pp = g_part[LAYER]
                        + (((size_t)b * NBLK + blockIdx.x) * 8 + gbase + tid) * 2;
            pp[0] = 0.f;
            pp[1] = 0.f;
        }
        return;
    }

    extern __shared__ unsigned char smraw[];
    float2* Wp     = (float2*)smraw;                                 // [C][64] {w,w}
    float*  Xs     = (float*)(smraw + sizeof(float2) * O * C);       // [C][128]
    float*  sScale = Xs + C * 128;
    float*  sShift = sScale + 64;
    float*  sWsum  = sShift + 64;

    const float* xin = (LAYER == 0) ? g_x0 : ((LAYER == 1) ? g_x1 : g_x2);
    const float* xbp = xin + (size_t)b * C * M_PER_B + m0;

    if (!GN_IN) {
        const uint32_t xs_u32 = smem_u32(Xs);
        for (int idx = tid; idx < C * 32; idx += NT) {
            int ci = idx >> 5;
            int c4 = (idx & 31) << 2;
            cp_async16(xs_u32 + (uint32_t)(ci * 128 + c4) * 4,
                       xbp + (size_t)ci * M_PER_B + c4);
        }
        CP_COMMIT();
        for (int idx = tid; idx < O * C; idx += NT) {
            int o = idx / C, c = idx - o * C;
            float w = W[idx];
            Wp[c * O + o] = make_float2(w, w);
        }
        CP_WAIT0();
        __syncthreads();
    } else {
        for (int idx = tid; idx < O * C; idx += NT) {
            int o = idx / C, c = idx - o * C;
            float w = W[idx];
            Wp[c * O + o] = make_float2(w, w);
        }
        if (tid < C) {
            const float* mr = g_mr[LAYER - 1] + b * 16;
            int gg = tid >> 3;
            float s = mr[gg * 2 + 1] * gamma[tid];
            sScale[tid] = s;
            sShift[tid] = beta[tid] - mr[gg * 2] * s;
        }
        __syncthreads();
        for (int idx = tid; idx < C * 32; idx += NT) {
            int ci = idx >> 5;
            int c4 = (idx & 31) << 2;
            float4 v = *(const float4*)&xbp[(size_t)ci * M_PER_B + c4];
            float s = sScale[ci], t = sShift[ci];
            v.x = fmaxf(s * v.x + t, 0.f);
            v.y = fmaxf(s * v.y + t, 0.f);
            v.z = fmaxf(s * v.z + t, 0.f);
            v.w = fmaxf(s * v.w + t, 0.f);
            *(float4*)&Xs[ci * 128 + c4] = v;
        }
        __syncthreads();
    }

    const int ob = tid >> 5;
    const int cg = tid & 31;
    const float* xcol = Xs + cg * 4;
    const unsigned long long* wb64 = (const unsigned long long*)Wp + ob * 8;

    unsigned long long acc[8][2];
#pragma unroll
    for (int a = 0; a < 8; a++) { acc[a][0] = 0ull; acc[a][1] = 0ull; }

#pragma unroll 4
    for (int i = 0; i < C; i++) {
        ulonglong2 y0 = *(const ulonglong2*)&xcol[i * 128];
        const ulonglong2* wr = (const ulonglong2*)(wb64 + (size_t)i * O);
        ulonglong2 w0 = wr[0], w1 = wr[1], w2 = wr[2], w3 = wr[3];
        FMA_CH4(w0, w1, w2, w3, y0);
    }

    // store raw outputs (compacted layout)
    float* xo = ((LAYER == 0) ? g_x1 : ((LAYER == 1) ? g_x2 : g_y2))
                + ((size_t)b * ((LAYER == 2) ? 128 : 64) + oofs) * M_PER_B
                + m0 + cg * 4;
#pragma unroll
    for (int oo = 0; oo < 8; oo++) {
        float4 v0;
        v0.x = lo32(acc[oo][0]); v0.y = hi32(acc[oo][0]);
        v0.z = lo32(acc[oo][1]); v0.w = hi32(acc[oo][1]);
        *(float4*)&xo[(size_t)(ob * 8 + oo) * M_PER_B] = v0;
    }

    // ---- weighted GN stats partials ----
    {
        const float* wtp = g_wt + (size_t)b * M_PER_B + m0 + cg * 4;
        float4 wa4 = *(const float4*)wtp;
        float wts[4] = {wa4.x, wa4.y, wa4.z, wa4.w};
        float colS[4] = {0, 0, 0, 0};
        float colQ[4] = {0, 0, 0, 0};
#pragma unroll
        for (int oo = 0; oo < 8; oo++) {
#pragma unroll
            for (int p = 0; p < 2; p++) {
                float v0 = lo32(acc[oo][p]), v1 = hi32(acc[oo][p]);
                colS[2 * p]     += v0;
                colQ[2 * p]     += v0 * v0;
                colS[2 * p + 1] += v1;
                colQ[2 * p + 1] += v1 * v1;
            }
        }
        float S = 0.f, Q = 0.f;
#pragma unroll
        for (int j = 0; j < 4; j++) {
            S += wts[j] * colS[j];
            Q += wts[j] * colQ[j];
        }
#pragma unroll
        for (int d = 16; d > 0; d >>= 1) {
            S += __shfl_xor_sync(0xffffffffu, S, d);
            Q += __shfl_xor_sync(0xffffffffu, Q, d);
        }
        if ((tid & 31) == 0) {
            sWsum[ob * 2 + 0] = S;
            sWsum[ob * 2 + 1] = Q;
        }
    }
    __syncthreads();
    if (tid < NG) {
        float S, Q;
        if (LAYER == 2) {      // group = 16 channels = 2 warps
            S = sWsum[(2 * tid) * 2 + 0] + sWsum[(2 * tid + 1) * 2 + 0];
            Q = sWsum[(2 * tid) * 2 + 1] + sWsum[(2 * tid + 1) * 2 + 1];
        } else {               // group = 8 channels = 1 warp
            S = sWsum[tid * 2 + 0];
            Q = sWsum[tid * 2 + 1];
        }
        float* pp = g_part[LAYER]
                    + (((size_t)b * NBLK + blockIdx.x) * 8 + gbase + tid) * 2;
        pp[0] = S;
        pp[1] = Q;
    }
}

// ---------------- per-(b,group) stats reduce ----------------
template <int LAYER>
__global__ void __launch_bounds__(256) reduce_stats_kernel()
{
    constexpr float INV = (LAYER == 2) ? (1.f / 2097152.f) : (1.f / 1048576.f);
    const int b = blockIdx.x >> 3, g = blockIdx.x & 7;
    __shared__ float sS[256], sQ[256];
    float S = 0.f, Q = 0.f;
    for (int mb = threadIdx.x; mb < NBLK; mb += 256) {
        const float* p = g_part[LAYER] + (((size_t)b * NBLK + mb) * 8 + g) * 2;
        S += p[0];
        Q += p[1];
    }
    sS[threadIdx.x] = S; sQ[threadIdx.x] = Q;
    __syncthreads();
    for (int d = 128; d > 0; d >>= 1) {
        if (threadIdx.x < d) {
            sS[threadIdx.x] += sS[threadIdx.x + d];
            sQ[threadIdx.x] += sQ[threadIdx.x + d];
        }
        __syncthreads();
    }
    if (threadIdx.x == 0) {
        float mean = sS[0] * INV;
        float var  = sQ[0] * INV - mean * mean;
        g_mr[LAYER][b * 16 + g * 2 + 0] = mean;
        g_mr[LAYER][b * 16 + g * 2 + 1] = rsqrtf(var + 1e-5f);
    }
}

// ---------------- segfinal v2: warp-per-point max/min + GN2 affine + output --
__global__ void __launch_bounds__(256) segfinal_kernel(
    const float* __restrict__ gamma, const float* __restrict__ beta,
    float* __restrict__ out)
{
    __shared__ float sTile[8][32 * 33];
    __shared__ float sRelu[8 * 130];
    __shared__ float sRaw[8 * 130];
    __shared__ float sSc[128], sSh[128];

    const int t    = threadIdx.x;
    const int warp = t >> 5;
    const int lane = t & 31;
    const int b    = blockIdx.y;
    const int n    = blockIdx.x * 8 + warp;

    if (t < 128) {
        int g = t >> 4;
        const float* mr = g_mr[2] + b * 16 + g * 2;
        float s = mr[1] * gamma[t];
        sSc[t] = s;
        sSh[t] = beta[t] - mr[0] * s;
    }
    __syncthreads();

    const int c   = g_cnt[b * NPTS + n];
    const int off = g_off[b * NPTS + n];
    const float* yb = g_y2 + (size_t)b * 128 * M_PER_B + off;
    float* tile = sTile[warp];
    const bool in = lane < c;

#pragma unroll
    for (int tt = 0; tt < 4; tt++) {
#pragma unroll
        for (int o = 0; o < 32; o++)
            tile[o * 33 + lane] = in ? yb[(size_t)(tt * 32 + o) * M_PER_B + lane] : 0.f;
        __syncwarp();

        const float* dp = tile + lane * 33;
        float mx = dp[0];
        float mn = mx;
        for (int k = 1; k < c; k++) {
            float v = dp[k];
            mx = fmaxf(mx, v);
            mn = fminf(mn, v);
        }
        int og = tt * 32 + lane;
        float s = sSc[og], sh = sSh[og];
        float v = (s >= 0.f) ? (s * mx + sh) : (s * mn + sh);
        sRelu[warp * 130 + og] = fmaxf(v, 0.f);
        sRaw [warp * 130 + og] = v;
        __syncwarp();
    }
    __syncthreads();

    const int n0 = blockIdx.x * 8;
    for (int idx = t; idx < 1024; idx += 256) {
        int o = idx >> 3, p = idx & 7;
        size_t oi = ((size_t)b * 128 + o) * NPTS + n0 + p;
        out[oi] = sRelu[p * 130 + o];
        out[(size_t)2 * 128 * NPTS + oi] = sRaw[p * 130 + o];
    }
}

// ---------------- launch ----------------
extern "C" void kernel_launch(void* const* d_in, const int* in_sizes, int n_in,
                              void* d_out, int out_size)
{
    const float* feature = (const float*)d_in[0];
    const float* xyz     = (const float*)d_in[1];
    const float* w0  = (const float*)d_in[2];
    const float* gg0 = (const float*)d_in[3];
    const float* gb0 = (const float*)d_in[4];
    const float* w1  = (const float*)d_in[5];
    const float* gg1 = (const float*)d_in[6];
    const float* gb1 = (const float*)d_in[7];
    const float* w2  = (const float*)d_in[8];
    const float* gg2 = (const float*)d_in[9];
    const float* gb2 = (const float*)d_in[10];
    const float* wa  = (const float*)d_in[11];
    const float* wb  = (const float*)d_in[12];
    const float* wc  = (const float*)d_in[13];
    float* out = (float*)d_out;

    const int sm0 = 64 * 13 * 8 + 13 * 128 * 4 + 512 + 64;
    const int sm1 = 64 * 64 * 8 + 64 * 128 * 4 + 512 + 64;
    cudaFuncSetAttribute(gemm_gn_kernel<0>, cudaFuncAttributeMaxDynamicSharedMemorySize, sm0);
    cudaFuncSetAttribute(gemm_gn_kernel<1>, cudaFuncAttributeMaxDynamicSharedMemorySize, sm1);
    cudaFuncSetAttribute(gemm_gn_kernel<2>, cudaFuncAttributeMaxDynamicSharedMemorySize, sm1);

    grid_build_kernel<<<2, 1024>>>(xyz);
    ballgrid_kernel<<<dim3(512, 2), 256>>>(xyz);
    scan_kernel<<<2, 1024>>>();
    feat_kernel<<<dim3(512, 2), 256>>>(xyz, feature, wa, wb, wc);

    gemm_gn_kernel<0><<<dim3(NBLK, 2), 256, sm0>>>(w0, gg0, gb0, 0, 0);
    reduce_stats_kernel<0><<<16, 256>>>();

    gemm_gn_kernel<1><<<dim3(NBLK, 2), 256, sm1>>>(w1, gg0, gb0, 0, 0);
    reduce_stats_kernel<1><<<16, 256>>>();

    gemm_gn_kernel<2><<<dim3(NBLK, 2), 256, sm1>>>(w2,            gg1, gb1, 0, 0);
    gemm_gn_kernel<2><<<dim3(NBLK, 2), 256, sm1>>>(w2 + 64 * 64,  gg1, gb1, 4, 64);
    reduce_stats_kernel<2><<<16, 256>>>();

    segfinal_kernel<<<dim3(512, 2), 256>>>(gg2, gb2, out);
}

// round 16
// speedup vs baseline: 1.1884x; 1.1884x over previous
#include <cuda_runtime.h>
#include <cstdint>
#include <cfloat>

#define NPTS 4096
#define BQ_K 32
#define M_PER_B (NPTS * BQ_K)   // max 131072 columns per batch
#define NBATCH 2
#define NCELL 1000               // 10x10x10 grid, cell = 0.1 = radius

// ---------------- scratch (device globals; no allocations) ----------------
__device__ float  g_x0[NBATCH * 13  * M_PER_B];
__device__ float  g_x1[NBATCH * 64  * M_PER_B];
__device__ float  g_x2[NBATCH * 64  * M_PER_B];
__device__ float  g_y2[NBATCH * 128 * M_PER_B];
__device__ float  g_wt[NBATCH * M_PER_B];
__device__ int    g_idx[NBATCH * NPTS * BQ_K];
__device__ int    g_cnt[NBATCH * NPTS];
__device__ int    g_off[NBATCH * NPTS];
__device__ int    g_meta[NBATCH * 2];
__device__ float  g_part[3][NBATCH * 512 * 8 * 2];
__device__ float  g_mr[3][NBATCH * 8 * 2];
__device__ int    g_cellOff[NBATCH][NCELL + 1];
__device__ float4 g_cellXYZ4[NBATCH * NPTS];     // cell-ordered {x,y,z,idx}

// ---------------- helpers ----------------
__device__ __forceinline__ float lo32(unsigned long long v) {
    return __uint_as_float((unsigned)(v & 0xffffffffull));
}
__device__ __forceinline__ float hi32(unsigned long long v) {
    return __uint_as_float((unsigned)(v >> 32));
}
__device__ __forceinline__ void ffma2(unsigned long long& a,
                                      unsigned long long w,
                                      unsigned long long y) {
    asm("fma.rn.f32x2 %0, %1, %2, %0;" : "+l"(a) : "l"(w), "l"(y));
}
__device__ __forceinline__ uint32_t smem_u32(const void* p) {
    uint32_t a;
    asm("{ .reg .u64 t; cvta.to.shared.u64 t, %1; cvt.u32.u64 %0, t; }"
        : "=r"(a) : "l"(p));
    return a;
}
__device__ __forceinline__ void cp_async16(uint32_t saddr, const void* gptr) {
    asm volatile("cp.async.cg.shared.global [%0], [%1], 16;"
                 :: "r"(saddr), "l"(gptr));
}
#define CP_COMMIT() asm volatile("cp.async.commit_group;")
#define CP_WAIT0()  asm volatile("cp.async.wait_group 0;")

__device__ __forceinline__ float angle3(float ax, float ay, float az,
                                        float bx, float by, float bz) {
    float cx = ay * bz - az * by;
    float cy = az * bx - ax * bz;
    float cz = ax * by - ay * bx;
    float s = cx * cx + cy * cy + cz * cz;
    float y = s > 0.f ? sqrtf(s) : 0.f;
    float x = ax * bx + ay * by + az * bz;
    if (y == 0.f && x == 0.f) return 0.f;
    return atan2f(y, x);
}
__device__ __forceinline__ int cell_of(float x, float y, float z) {
    int cx = (int)(x * 10.f); cx = cx < 0 ? 0 : (cx > 9 ? 9 : cx);
    int cy = (int)(y * 10.f); cy = cy < 0 ? 0 : (cy > 9 ? 9 : cy);
    int cz = (int)(z * 10.f); cz = cz < 0 ? 0 : (cz > 9 ? 9 : cz);
    return (cz * 10 + cy) * 10 + cx;
}

// ---------------- K0: grid build (one block per batch) ----------------
__global__ void __launch_bounds__(1024) grid_build_kernel(
    const float* __restrict__ xyz)
{
    __shared__ int scnt[NCELL];
    __shared__ int sp[1024];
    __shared__ int sbase[NCELL];

    const int b = blockIdx.x;
    const int t = threadIdx.x;
    const float* xb = xyz + (size_t)b * NPTS * 3;

    if (t < NCELL) scnt[t] = 0;
    __syncthreads();

    float px[4], py[4], pz[4];
    int cells[4];
#pragma unroll
    for (int q = 0; q < 4; q++) {
        int i = t * 4 + q;
        px[q] = xb[i * 3 + 0];
        py[q] = xb[i * 3 + 1];
        pz[q] = xb[i * 3 + 2];
        cells[q] = cell_of(px[q], py[q], pz[q]);
        atomicAdd(&scnt[cells[q]], 1);
    }
    __syncthreads();

    sp[t] = (t < NCELL) ? scnt[t] : 0;
    __syncthreads();
    for (int d = 1; d < 1024; d <<= 1) {
        int u = (t >= d) ? sp[t - d] : 0;
        __syncthreads();
        sp[t] += u;
        __syncthreads();
    }
    if (t < NCELL) {
        int e = (t > 0) ? sp[t - 1] : 0;
        sbase[t] = e;
        scnt[t] = 0;
        g_cellOff[b][t] = e;
    }
    if (t == 0) g_cellOff[b][NCELL] = NPTS;
    __syncthreads();

#pragma unroll
    for (int q = 0; q < 4; q++) {
        int i = t * 4 + q;
        int c = cells[q];
        int pos = sbase[c] + atomicAdd(&scnt[c], 1);
        g_cellXYZ4[b * NPTS + pos] =
            make_float4(px[q], py[q], pz[q], __int_as_float(i));
    }
}

// ---------------- K1: ball query via grid (warp per point) ----------------
__global__ void __launch_bounds__(256) ballgrid_kernel(
    const float* __restrict__ xyz)
{
    __shared__ int hitbuf[8][96];

    const int b    = blockIdx.y;
    const int warp = threadIdx.x >> 5;
    const int lane = threadIdx.x & 31;
    const int i    = blockIdx.x * 8 + warp;

    const float cx = __ldg(xyz + ((size_t)b * NPTS + i) * 3 + 0);
    const float cy = __ldg(xyz + ((size_t)b * NPTS + i) * 3 + 1);
    const float cz = __ldg(xyz + ((size_t)b * NPTS + i) * 3 + 2);
    const float R2 = (float)(0.1 * 0.1);

    int cxi = (int)(cx * 10.f); cxi = cxi < 0 ? 0 : (cxi > 9 ? 9 : cxi);
    int cyi = (int)(cy * 10.f); cyi = cyi < 0 ? 0 : (cyi > 9 ? 9 : cyi);
    int czi = (int)(cz * 10.f); czi = czi < 0 ? 0 : (czi > 9 ? 9 : czi);
    const int x0 = cxi > 0 ? cxi - 1 : 0;
    const int x1 = cxi < 9 ? cxi + 1 : 9;

    int* hb = hitbuf[warp];
    int nh = 0;
    const float4* cxyz = g_cellXYZ4 + (size_t)b * NPTS;

    for (int dz = -1; dz <= 1; dz++) {
        int z = czi + dz;
        if (z < 0 || z > 9) continue;
        for (int dy = -1; dy <= 1; dy++) {
            int y = cyi + dy;
            if (y < 0 || y > 9) continue;
            int row = (z * 10 + y) * 10;
            int s = g_cellOff[b][row + x0];
            int e = g_cellOff[b][row + x1 + 1];
            for (int base = s; base < e; base += 32) {
                int idx = base + lane;
                bool v = idx < e;
                float4 q = v ? __ldg(cxyz + idx) : make_float4(9.f, 9.f, 9.f, 0.f);
                float dx = q.x - cx;
                float dyv = q.y - cy;
                float dzv = q.z - cz;
                float d2 = __fadd_rn(__fadd_rn(__fmul_rn(dx, dx),
                                               __fmul_rn(dyv, dyv)),
                                     __fmul_rn(dzv, dzv));
                bool hit = v && (d2 <= R2);
                unsigned m = __ballot_sync(0xffffffffu, hit);
                if (hit) {
                    int pos = nh + __popc(m & ((1u << lane) - 1u));
                    if (pos < 96) hb[pos] = __float_as_int(q.w);
                }
                nh += __popc(m);
            }
        }
    }
    __syncwarp();

    int c;
    if (nh <= 32) {
        int v = (lane < nh) ? hb[lane] : 0x7fffffff;
#pragma unroll
        for (int k = 2; k <= 32; k <<= 1) {
#pragma unroll
            for (int j = k >> 1; j > 0; j >>= 1) {
                int v2 = __shfl_xor_sync(0xffffffffu, v, j);
                bool lower = (lane & j) == 0;
                bool asc   = (lane & k) == 0;
                v = ((asc == lower) == (v < v2)) ? v
                    : (((asc == lower)) ? min(v, v2) : max(v, v2));
            }
        }
        c = nh;
        if (lane < c) g_idx[((size_t)b * NPTS + i) * BQ_K + lane] = v;
    } else {
        if (lane == 0) {
            int n = nh < 96 ? nh : 96;
            for (int a = 1; a < n; a++) {
                int key = hb[a];
                int p = a - 1;
                while (p >= 0 && hb[p] > key) { hb[p + 1] = hb[p]; p--; }
                hb[p + 1] = key;
            }
        }
        __syncwarp();
        c = BQ_K;
        g_idx[((size_t)b * NPTS + i) * BQ_K + lane] = hb[lane];
    }
    if (lane == 0) g_cnt[b * NPTS + i] = c;
}

// ---------------- K2: deterministic block scan of counts (+ tail zeroing) ----
__global__ void __launch_bounds__(1024) scan_kernel()
{
    __shared__ int sp[1024];
    const int t = threadIdx.x;
    const int b = blockIdx.x;
    int4 cv = ((const int4*)(g_cnt + b * NPTS))[t];
    int s0 = cv.x;
    int s1 = s0 + cv.y;
    int s2 = s1 + cv.z;
    int s3 = s2 + cv.w;
    sp[t] = s3;
    __syncthreads();
    for (int d = 1; d < 1024; d <<= 1) {
        int u = (t >= d) ? sp[t - d] : 0;
        __syncthreads();
        sp[t] += u;
        __syncthreads();
    }
    int e = (t > 0) ? sp[t - 1] : 0;
    int base = b * NPTS + t * 4;
    g_off[base + 0] = e;
    g_off[base + 1] = e + s0;
    g_off[base + 2] = e + s1;
    g_off[base + 3] = e + s2;
    int tot = sp[1023];
    int pad = (tot + 255) & ~255;
    if (t == 0) {
        g_meta[b * 2 + 0] = tot;
        g_meta[b * 2 + 1] = pad;
    }
    for (int col = tot + t; col < pad; col += 1024) {
        float* o = g_x0 + (size_t)b * 13 * M_PER_B + col;
#pragma unroll
        for (int r = 0; r < 13; r++) o[r * M_PER_B] = 0.f;
        g_wt[(size_t)b * M_PER_B + col] = 0.f;
    }
}

// ---------------- K3: compacted 13-ch features + weights ----------------
__global__ void __launch_bounds__(256) feat_kernel(
    const float* __restrict__ xyz, const float* __restrict__ feat,
    const float* __restrict__ wa, const float* __restrict__ wb,
    const float* __restrict__ wc)
{
    const int b = blockIdx.y;
    const int warp = threadIdx.x >> 5;
    const int lane = threadIdx.x & 31;
    const int i = blockIdx.x * 8 + warp;

    const int c   = g_cnt[b * NPTS + i];
    const int off = g_off[b * NPTS + i];
    if (lane >= c) return;

    const float* xb = xyz + (size_t)b * NPTS * 3;
    const float* fb = feat + (size_t)b * NPTS * 3;
    int j = g_idx[((size_t)b * NPTS + i) * BQ_K + lane];

    float cx = __ldg(xb + i * 3 + 0), cy = __ldg(xb + i * 3 + 1), cz = __ldg(xb + i * 3 + 2);
    float gx = __ldg(xb + j * 3 + 0), gy = __ldg(xb + j * 3 + 1), gz = __ldg(xb + j * 3 + 2);
    float nx = __ldg(fb + j * 3 + 0), ny = __ldg(fb + j * 3 + 1), nz = __ldg(fb + j * 3 + 2);
    float rx = __ldg(fb + i * 3 + 0), ry = __ldg(fb + i * 3 + 1), rz = __ldg(fb + i * 3 + 2);
    float dx = gx - cx, dy = gy - cy, dz = gz - cz;
    float sq = dx * dx + dy * dy + dz * dz;
    float dist = sq > 0.f ? sqrtf(sq) : 0.f;
    float a1 = angle3(rx, ry, rz, dx, dy, dz);
    float a2 = angle3(nx, ny, nz, dx, dy, dz);
    float a3 = angle3(rx, ry, rz, nx, ny, nz);
    float A = __ldg(wa), Bv = __ldg(wb), Cv = __ldg(wc);

    int col = off + lane;
    float* o = g_x0 + (size_t)b * 13 * M_PER_B + col;
    o[0 * M_PER_B]  = A * cx;  o[1 * M_PER_B]  = A * cy;  o[2 * M_PER_B]  = A * cz;
    o[3 * M_PER_B]  = A * gx;  o[4 * M_PER_B]  = A * gy;  o[5 * M_PER_B]  = A * gz;
    o[6 * M_PER_B]  = Bv * dx; o[7 * M_PER_B]  = Bv * dy; o[8 * M_PER_B]  = Bv * dz;
    o[9 * M_PER_B]  = Bv * dist;
    o[10 * M_PER_B] = Cv * a1; o[11 * M_PER_B] = Cv * a2; o[12 * M_PER_B] = Cv * a3;
    g_wt[(size_t)b * M_PER_B + col] = (lane == 0) ? (float)(33 - c) : 1.f;
}

// 32 FFMA2 block: 8 outputs x 8 cols
#define FMA_CH(W0, W1, W2, W3, Y0, Y1)            \
    do {                                          \
        ffma2(acc[0][0], (W0).x, (Y0).x);         \
        ffma2(acc[0][1], (W0).x, (Y0).y);         \
        ffma2(acc[0][2], (W0).x, (Y1).x);         \
        ffma2(acc[0][3], (W0).x, (Y1).y);         \
        ffma2(acc[1][0], (W0).y, (Y0).x);         \
        ffma2(acc[1][1], (W0).y, (Y0).y);         \
        ffma2(acc[1][2], (W0).y, (Y1).x);         \
        ffma2(acc[1][3], (W0).y, (Y1).y);         \
        ffma2(acc[2][0], (W1).x, (Y0).x);         \
        ffma2(acc[2][1], (W1).x, (Y0).y);         \
        ffma2(acc[2][2], (W1).x, (Y1).x);         \
        ffma2(acc[2][3], (W1).x, (Y1).y);         \
        ffma2(acc[3][0], (W1).y, (Y0).x);         \
        ffma2(acc[3][1], (W1).y, (Y0).y);         \
        ffma2(acc[3][2], (W1).y, (Y1).x);         \
        ffma2(acc[3][3], (W1).y, (Y1).y);         \
        ffma2(acc[4][0], (W2).x, (Y0).x);         \
        ffma2(acc[4][1], (W2).x, (Y0).y);         \
        ffma2(acc[4][2], (W2).x, (Y1).x);         \
        ffma2(acc[4][3], (W2).x, (Y1).y);         \
        ffma2(acc[5][0], (W2).y, (Y0).x);         \
        ffma2(acc[5][1], (W2).y, (Y0).y);         \
        ffma2(acc[5][2], (W2).y, (Y1).x);         \
        ffma2(acc[5][3], (W2).y, (Y1).y);         \
        ffma2(acc[6][0], (W3).x, (Y0).x);         \
        ffma2(acc[6][1], (W3).x, (Y0).y);         \
        ffma2(acc[6][2], (W3).x, (Y1).x);         \
        ffma2(acc[6][3], (W3).x, (Y1).y);         \
        ffma2(acc[7][0], (W3).y, (Y0).x);         \
        ffma2(acc[7][1], (W3).y, (Y0).y);         \
        ffma2(acc[7][2], (W3).y, (Y1).x);         \
        ffma2(acc[7][3], (W3).y, (Y1).y);         \
    } while (0)

// ---------------- fused GEMM + input GN/ReLU + weighted stats ---------------
// Layer 0: cp.async staging. Layers 1/2: 8-chunk software-pipelined staging
// (next chunk's LDGs issue before current chunk's transform+STS+compute, so
// global-load latency hides behind FFMA2 work).
template <int LAYER>
__global__ void __launch_bounds__(LAYER == 2 ? 512 : 256, LAYER == 2 ? 1 : 2)
gemm_gn_kernel(const float* __restrict__ W, const float* __restrict__ gamma,
               const float* __restrict__ beta)
{
    constexpr int C     = (LAYER == 0) ? 13 : 64;
    constexpr int O     = (LAYER == 2) ? 128 : 64;
    constexpr int NT    = (LAYER == 2) ? 512 : 256;
    constexpr bool GN_IN = (LAYER > 0);

    const int tid = threadIdx.x;
    const int b   = blockIdx.y;
    const int m0  = blockIdx.x * 256;

    if (m0 >= g_meta[b * 2 + 1]) {
        if (tid < 8) {
            float* pp = g_part[LAYER]
                        + (((size_t)b * gridDim.x + blockIdx.x) * 8 + tid) * 2;
            pp[0] = 0.f;
            pp[1] = 0.f;
        }
        return;
    }

    extern __shared__ unsigned char smraw[];
    float2* Wp     = (float2*)smraw;                                 // [C][O] {w,w}
    float*  Xs     = (float*)(smraw + sizeof(float2) * O * C);       // [C][256]
    float*  sScale = Xs + C * 256;
    float*  sShift = sScale + 64;
    float*  sWsum  = sShift + 64;

    const float* xin = (LAYER == 0) ? g_x0 : ((LAYER == 1) ? g_x1 : g_x2);
    const float* xbp = xin + (size_t)b * C * M_PER_B + m0;

    const int ob = tid >> 5;
    const int cg = tid & 31;
    const float* xcol = Xs + cg * 4;
    const unsigned long long* wb64;

    unsigned long long acc[8][4];
#pragma unroll
    for (int a = 0; a < 8; a++) {
        acc[a][0] = 0ull; acc[a][1] = 0ull; acc[a][2] = 0ull; acc[a][3] = 0ull;
    }

    if (!GN_IN) {
        const uint32_t xs_u32 = smem_u32(Xs);
        for (int idx = tid; idx < C * 64; idx += NT) {
            int ci = idx >> 6;
            int c4 = (idx & 63) << 2;
            cp_async16(xs_u32 + (uint32_t)(ci * 256 + c4) * 4,
                       xbp + (size_t)ci * M_PER_B + c4);
        }
        CP_COMMIT();
        for (int idx = tid; idx < O * C; idx += NT) {
            int o = idx / C, c = idx - o * C;
            float w = W[idx];
            Wp[c * O + o] = make_float2(w, w);
        }
        CP_WAIT0();
        __syncthreads();

        wb64 = (const unsigned long long*)Wp + ob * 8;
#pragma unroll 4
        for (int i = 0; i < C; i++) {
            ulonglong2 y0 = *(const ulonglong2*)&xcol[i * 256];
            ulonglong2 y1 = *(const ulonglong2*)&xcol[i * 256 + 128];
            const ulonglong2* wr = (const ulonglong2*)(wb64 + (size_t)i * O);
            ulonglong2 w0 = wr[0], w1 = wr[1], w2 = wr[2], w3 = wr[3];
            FMA_CH(w0, w1, w2, w3, y0, y1);
        }
    } else {
        // ---- W staging + GN prep ----
        for (int idx = tid; idx < O * C; idx += NT) {
            int o = idx / C, c = idx - o * C;
            float w = W[idx];
            Wp[c * O + o] = make_float2(w, w);
        }
        if (tid < C) {
            const float* mr = g_mr[LAYER - 1] + b * 16;
            int gg = tid >> 3;
            float s = mr[gg * 2 + 1] * gamma[tid];
            sScale[tid] = s;
            sShift[tid] = beta[tid] - mr[gg * 2] * s;
        }
        __syncthreads();
        wb64 = (const unsigned long long*)Wp + ob * 8;

        // 8-chunk pipeline: each thread stages 2 float4 per 8-channel chunk.
        const int ciA  = (tid & (NT - 1)) >> 6;   // 0..3 (NT=256) / 0..7 (512)
        // For NT=512, threads cover 8 rows per chunk directly.
        constexpr int ROWS = NT / 64;             // rows staged per pass (4 or 8)
        const int rA   = tid >> 6;                // 0..ROWS-1
        const int colA = (tid & 63) << 2;
        (void)ciA;

        float4 A0, A1, B0, B1;
        if (ROWS == 4) {
            A0 = *(const float4*)&xbp[(size_t)(rA)     * M_PER_B + colA];
            A1 = *(const float4*)&xbp[(size_t)(rA + 4) * M_PER_B + colA];
        } else {
            A0 = *(const float4*)&xbp[(size_t)(rA) * M_PER_B + colA];
        }

#pragma unroll
        for (int ck = 0; ck < 8; ck++) {
            // prefetch next chunk
            if (ck < 7) {
                if (ROWS == 4) {
                    B0 = *(const float4*)&xbp[(size_t)(ck * 8 + 8 + rA)  * M_PER_B + colA];
                    B1 = *(const float4*)&xbp[(size_t)(ck * 8 + 12 + rA) * M_PER_B + colA];
                } else {
                    B0 = *(const float4*)&xbp[(size_t)(ck * 8 + 8 + rA) * M_PER_B + colA];
                }
            }
            // transform + STS current chunk
            {
                int c0 = ck * 8 + rA;
                float s0 = sScale[c0], t0 = sShift[c0];
                float4 v0 = A0;
                v0.x = fmaxf(s0 * v0.x + t0, 0.f);
                v0.y = fmaxf(s0 * v0.y + t0, 0.f);
                v0.z = fmaxf(s0 * v0.z + t0, 0.f);
                v0.w = fmaxf(s0 * v0.w + t0, 0.f);
                *(float4*)&Xs[c0 * 256 + colA] = v0;
                if (ROWS == 4) {
                    int c1 = c0 + 4;
                    float s1 = sScale[c1], t1 = sShift[c1];
                    float4 v1 = A1;
                    v1.x = fmaxf(s1 * v1.x + t1, 0.f);
                    v1.y = fmaxf(s1 * v1.y + t1, 0.f);
                    v1.z = fmaxf(s1 * v1.z + t1, 0.f);
                    v1.w = fmaxf(s1 * v1.w + t1, 0.f);
                    *(float4*)&Xs[c1 * 256 + colA] = v1;
                }
            }
            __syncthreads();
            // compute current chunk (8 channels)
#pragma unroll
            for (int ii = 0; ii < 8; ii++) {
                const int i = ck * 8 + ii;
                ulonglong2 y0 = *(const ulonglong2*)&xcol[i * 256];
                ulonglong2 y1 = *(const ulonglong2*)&xcol[i * 256 + 128];
                const ulonglong2* wr = (const ulonglong2*)(wb64 + (size_t)i * O);
                ulonglong2 w0 = wr[0], w1 = wr[1], w2 = wr[2], w3 = wr[3];
                FMA_CH(w0, w1, w2, w3, y0, y1);
            }
            A0 = B0;
            A1 = B1;
        }
    }

    // ---- store raw outputs (compacted layout) ----
    float* xo = ((LAYER == 0) ? g_x1 : ((LAYER == 1) ? g_x2 : g_y2))
                + (size_t)b * O * M_PER_B + m0 + cg * 4;
#pragma unroll
    for (int oo = 0; oo < 8; oo++) {
        float4 v0, v1;
        v0.x = lo32(acc[oo][0]); v0.y = hi32(acc[oo][0]);
        v0.z = lo32(acc[oo][1]); v0.w = hi32(acc[oo][1]);
        v1.x = lo32(acc[oo][2]); v1.y = hi32(acc[oo][2]);
        v1.z = lo32(acc[oo][3]); v1.w = hi32(acc[oo][3]);
        *(float4*)&xo[(size_t)(ob * 8 + oo) * M_PER_B]       = v0;
        *(float4*)&xo[(size_t)(ob * 8 + oo) * M_PER_B + 128] = v1;
    }

    // ---- weighted GN stats ----
    {
        const float* wtp = g_wt + (size_t)b * M_PER_B + m0 + cg * 4;
        float4 wa4 = *(const float4*)wtp;
        float4 wb4 = *(const float4*)(wtp + 128);
        float wts[8] = {wa4.x, wa4.y, wa4.z, wa4.w, wb4.x, wb4.y, wb4.z, wb4.w};
        float colS[8] = {0, 0, 0, 0, 0, 0, 0, 0};
        float colQ[8] = {0, 0, 0, 0, 0, 0, 0, 0};
#pragma unroll
        for (int oo = 0; oo < 8; oo++) {
#pragma unroll
            for (int p = 0; p < 4; p++) {
                float v0 = lo32(acc[oo][p]), v1 = hi32(acc[oo][p]);
                colS[2 * p]     += v0;
                colQ[2 * p]     += v0 * v0;
                colS[2 * p + 1] += v1;
                colQ[2 * p + 1] += v1 * v1;
            }
        }
        float S = 0.f, Q = 0.f;
#pragma unroll
        for (int j = 0; j < 8; j++) {
            S += wts[j] * colS[j];
            Q += wts[j] * colQ[j];
        }
#pragma unroll
        for (int d = 16; d > 0; d >>= 1) {
            S += __shfl_xor_sync(0xffffffffu, S, d);
            Q += __shfl_xor_sync(0xffffffffu, Q, d);
        }
        if ((tid & 31) == 0) {
            sWsum[ob * 2 + 0] = S;
            sWsum[ob * 2 + 1] = Q;
        }
    }
    __syncthreads();
    if (tid < 8) {
        float S, Q;
        if (O == 64) {
            S = sWsum[tid * 2 + 0];
            Q = sWsum[tid * 2 + 1];
        } else {
            S = sWsum[(2 * tid) * 2 + 0] + sWsum[(2 * tid + 1) * 2 + 0];
            Q = sWsum[(2 * tid) * 2 + 1] + sWsum[(2 * tid + 1) * 2 + 1];
        }
        float* pp = g_part[LAYER] + (((size_t)b * gridDim.x + blockIdx.x) * 8 + tid) * 2;
        pp[0] = S;
        pp[1] = Q;
    }
}

// ---------------- per-(b,group) stats reduce ----------------
template <int LAYER>
__global__ void __launch_bounds__(256) reduce_stats_kernel()
{
    constexpr float INV = (LAYER == 2) ? (1.f / 2097152.f) : (1.f / 1048576.f);
    const int b = blockIdx.x >> 3, g = blockIdx.x & 7;
    __shared__ float sS[256], sQ[256];
    float S = 0.f, Q = 0.f;
    for (int mb = threadIdx.x; mb < 512; mb += 256) {
        const float* p = g_part[LAYER] + (((size_t)b * 512 + mb) * 8 + g) * 2;
        S += p[0];
        Q += p[1];
    }
    sS[threadIdx.x] = S; sQ[threadIdx.x] = Q;
    __syncthreads();
    for (int d = 128; d > 0; d >>= 1) {
        if (threadIdx.x < d) {
            sS[threadIdx.x] += sS[threadIdx.x + d];
            sQ[threadIdx.x] += sQ[threadIdx.x + d];
        }
        __syncthreads();
    }
    if (threadIdx.x == 0) {
        float mean = sS[0] * INV;
        float var  = sQ[0] * INV - mean * mean;
        g_mr[LAYER][b * 16 + g * 2 + 0] = mean;
        g_mr[LAYER][b * 16 + g * 2 + 1] = rsqrtf(var + 1e-5f);
    }
}

// ---------------- segfinal v2: warp-per-point max/min + GN2 affine + output --
__global__ void __launch_bounds__(256) segfinal_kernel(
    const float* __restrict__ gamma, const float* __restrict__ beta,
    float* __restrict__ out)
{
    __shared__ float sTile[8][32 * 33];
    __shared__ float sRelu[8 * 130];
    __shared__ float sRaw[8 * 130];
    __shared__ float sSc[128], sSh[128];

    const int t    = threadIdx.x;
    const int warp = t >> 5;
    const int lane = t & 31;
    const int b    = blockIdx.y;
    const int n    = blockIdx.x * 8 + warp;

    if (t < 128) {
        int g = t >> 4;
        const float* mr = g_mr[2] + b * 16 + g * 2;
        float s = mr[1] * gamma[t];
        sSc[t] = s;
        sSh[t] = beta[t] - mr[0] * s;
    }
    __syncthreads();

    const int c   = g_cnt[b * NPTS + n];
    const int off = g_off[b * NPTS + n];
    const float* yb = g_y2 + (size_t)b * 128 * M_PER_B + off;
    float* tile = sTile[warp];
    const bool in = lane < c;

#pragma unroll
    for (int tt = 0; tt < 4; tt++) {
#pragma unroll
        for (int o = 0; o < 32; o++)
            tile[o * 33 + lane] = in ? yb[(size_t)(tt * 32 + o) * M_PER_B + lane] : 0.f;
        __syncwarp();

        const float* dp = tile + lane * 33;
        float mx = dp[0];
        float mn = mx;
        for (int k = 1; k < c; k++) {
            float v = dp[k];
            mx = fmaxf(mx, v);
            mn = fminf(mn, v);
        }
        int og = tt * 32 + lane;
        float s = sSc[og], sh = sSh[og];
        float v = (s >= 0.f) ? (s * mx + sh) : (s * mn + sh);
        sRelu[warp * 130 + og] = fmaxf(v, 0.f);
        sRaw [warp * 130 + og] = v;
        __syncwarp();
    }
    __syncthreads();

    const int n0 = blockIdx.x * 8;
    for (int idx = t; idx < 1024; idx += 256) {
        int o = idx >> 3, p = idx & 7;
        size_t oi = ((size_t)b * 128 + o) * NPTS + n0 + p;
        out[oi] = sRelu[p * 130 + o];
        out[(size_t)2 * 128 * NPTS + oi] = sRaw[p * 130 + o];
    }
}

// ---------------- launch ----------------
extern "C" void kernel_launch(void* const* d_in, const int* in_sizes, int n_in,
                              void* d_out, int out_size)
{
    const float* feature = (const float*)d_in[0];
    const float* xyz     = (const float*)d_in[1];
    const float* w0  = (const float*)d_in[2];
    const float* gg0 = (const float*)d_in[3];
    const float* gb0 = (const float*)d_in[4];
    const float* w1  = (const float*)d_in[5];
    const float* gg1 = (const float*)d_in[6];
    const float* gb1 = (const float*)d_in[7];
    const float* w2  = (const float*)d_in[8];
    const float* gg2 = (const float*)d_in[9];
    const float* gb2 = (const float*)d_in[10];
    const float* wa  = (const float*)d_in[11];
    const float* wb  = (const float*)d_in[12];
    const float* wc  = (const float*)d_in[13];
    float* out = (float*)d_out;

    const int sm0 = 64 * 13 * 8   + 13 * 256 * 4 + 512 + 8 * 8;
    const int sm1 = 64 * 64 * 8   + 64 * 256 * 4 + 512 + 8 * 8;
    const int sm2 = 128 * 64 * 8  + 64 * 256 * 4 + 512 + 16 * 8;
    cudaFuncSetAttribute(gemm_gn_kernel<0>, cudaFuncAttributeMaxDynamicSharedMemorySize, sm0);
    cudaFuncSetAttribute(gemm_gn_kernel<1>, cudaFuncAttributeMaxDynamicSharedMemorySize, sm1);
    cudaFuncSetAttribute(gemm_gn_kernel<2>, cudaFuncAttributeMaxDynamicSharedMemorySize, sm2);

    grid_build_kernel<<<2, 1024>>>(xyz);
    ballgrid_kernel<<<dim3(512, 2), 256>>>(xyz);
    scan_kernel<<<2, 1024>>>();
    feat_kernel<<<dim3(512, 2), 256>>>(xyz, feature, wa, wb, wc);

    gemm_gn_kernel<0><<<dim3(512, 2), 256, sm0>>>(w0, gg0, gb0);
    reduce_stats_kernel<0><<<16, 256>>>();

    gemm_gn_kernel<1><<<dim3(512, 2), 256, sm1>>>(w1, gg0, gb0);
    reduce_stats_kernel<1><<<16, 256>>>();

    gemm_gn_kernel<2><<<dim3(512, 2), 512, sm2>>>(w2, gg1, gb1);
    reduce_stats_kernel<2><<<16, 256>>>();

    segfinal_kernel<<<dim3(512, 2), 256>>>(gg2, gb2, out);
}